// round 13
// baseline (speedup 1.0000x reference)
#include <cuda_runtime.h>
#include <cuda_bf16.h>
#include <cstdint>

// ---------------------------------------------------------------------------
// T2FN: fusion = sum_t (a1 ⊗ v1 ⊗ x1)  [B, 49*49*97], then 3-layer MLP.
// Stage 1 (fusion_mma): per-b GEMM av[2401x64] @ x1[64x97] on mma.sync
//   (bf16 3-pass hi/lo split, fp32 acc). A fragments built in registers from
//   fp32 a/v smem (no A smem); B (x1) staged bf16 hi/lo + ldmatrix.x4.trans.
// Stage 2 (gemm_mma): split-K GEMM fusion[128,FD] @ W1[FD,128], mma.sync,
//   3-pass bf16 split (unchanged R11 winner).
// Stage 3 (mlp): reduce partials + bias/relu chain + sigmoid*6-3.
// NOTE: tcgen05 unavailable (harness targets compute_103, not 103a).
// ---------------------------------------------------------------------------

typedef unsigned long long u64;

constexpr int B_  = 128;
constexpr int T_  = 64;
constexpr int A_  = 48;
constexpr int V_  = 48;
constexpr int X_  = 96;
constexpr int AI  = A_ + 1;      // 49
constexpr int VJ  = V_ + 1;      // 49
constexpr int XK  = X_ + 1;      // 97
constexpr int IJ  = AI * VJ;     // 2401
constexpr int FD  = IJ * XK;     // 232897
constexpr int FDP2 = 232960;     // FD padded to multiple of 64
constexpr int PF  = 128;
constexpr int NSPLIT = 296;      // K-slices
constexpr int KT  = 32;          // GEMM K-tile
constexpr int NT32 = FDP2 / KT;  // 7280

__device__ float g_fusion[(size_t)B_ * FDP2];        // ~119 MB (pad stays 0)
__device__ float g_part[(size_t)NSPLIT * B_ * PF];   // ~19.4 MB

// ---------------------------------------------------------------------------
// common mma helpers
// ---------------------------------------------------------------------------
__device__ __forceinline__ uint32_t smem_u32(const void* p) {
    uint32_t a;
    asm("{ .reg .u64 t; cvta.to.shared.u64 t, %1; cvt.u32.u64 %0, t; }"
        : "=r"(a) : "l"(p));
    return a;
}
__device__ __forceinline__ void ldsm_x4(uint32_t& r0, uint32_t& r1,
                                        uint32_t& r2, uint32_t& r3,
                                        uint32_t addr) {
    asm volatile("ldmatrix.sync.aligned.m8n8.x4.shared.b16 {%0,%1,%2,%3}, [%4];"
                 : "=r"(r0), "=r"(r1), "=r"(r2), "=r"(r3) : "r"(addr));
}
__device__ __forceinline__ void ldsm_x4t(uint32_t& r0, uint32_t& r1,
                                         uint32_t& r2, uint32_t& r3,
                                         uint32_t addr) {
    asm volatile("ldmatrix.sync.aligned.m8n8.x4.trans.shared.b16 {%0,%1,%2,%3}, [%4];"
                 : "=r"(r0), "=r"(r1), "=r"(r2), "=r"(r3) : "r"(addr));
}
__device__ __forceinline__ void mma16816(float* c, const uint32_t* a,
                                         const uint32_t* b) {
    asm volatile(
        "mma.sync.aligned.m16n8k16.row.col.f32.bf16.bf16.f32 "
        "{%0,%1,%2,%3}, {%4,%5,%6,%7}, {%8,%9}, {%0,%1,%2,%3};"
        : "+f"(c[0]), "+f"(c[1]), "+f"(c[2]), "+f"(c[3])
        : "r"(a[0]), "r"(a[1]), "r"(a[2]), "r"(a[3]), "r"(b[0]), "r"(b[1]));
}
__device__ __forceinline__ void split4(float4 v, uint2& hi, uint2& lo) {
    __nv_bfloat162 h01 = __float22bfloat162_rn(make_float2(v.x, v.y));
    __nv_bfloat162 h23 = __float22bfloat162_rn(make_float2(v.z, v.w));
    __nv_bfloat162 l01 = __float22bfloat162_rn(make_float2(
        v.x - __bfloat162float(h01.x), v.y - __bfloat162float(h01.y)));
    __nv_bfloat162 l23 = __float22bfloat162_rn(make_float2(
        v.z - __bfloat162float(h23.x), v.w - __bfloat162float(h23.y)));
    hi = make_uint2(*(uint32_t*)&h01, *(uint32_t*)&h23);
    lo = make_uint2(*(uint32_t*)&l01, *(uint32_t*)&l23);
}
__device__ __forceinline__ void split2(float f0, float f1,
                                       uint32_t& h, uint32_t& l) {
    __nv_bfloat162 hh = __float22bfloat162_rn(make_float2(f0, f1));
    __nv_bfloat162 ll = __float22bfloat162_rn(make_float2(
        f0 - __bfloat162float(hh.x), f1 - __bfloat162float(hh.y)));
    h = *(uint32_t*)&hh;
    l = *(uint32_t*)&ll;
}

// ---------------------------------------------------------------------------
// Stage 1: fusion via mma.sync. grid = (19 ij-tiles, 128 b), 256 threads.
// CTA tile 128 ij x 128 k (valid k < 97), K = 64 t. Warp tile 32 ij x 64 k.
// ---------------------------------------------------------------------------
constexpr int FS_AS = 0;                   // [64][50] fp32  (12800 B)
constexpr int FS_VS = 12800;               // [64][50] fp32  (12800 B)
constexpr int FS_BH = 25600;               // [64][136] bf16 (17408 B)
constexpr int FS_BL = 43008;               // [64][136] bf16 (17408 B)
constexpr int FS_TOTAL = 60416;

__global__ void __launch_bounds__(256)
fusion_mma(const float* __restrict__ audio,
           const float* __restrict__ video,
           const float* __restrict__ text)
{
    extern __shared__ __align__(16) char sm[];
    float* a_s = (float*)(sm + FS_AS);
    float* v_s = (float*)(sm + FS_VS);
    __nv_bfloat16* Bh = (__nv_bfloat16*)(sm + FS_BH);
    __nv_bfloat16* Bl = (__nv_bfloat16*)(sm + FS_BL);

    const int b      = blockIdx.y;
    const int ijbase = blockIdx.x * 128;
    const int tid    = threadIdx.x;
    const int wid    = tid >> 5;
    const int lane   = tid & 31;
    const int warp_ij = (wid >> 1) * 32;   // 4 ij-warps
    const int warp_k  = (wid & 1) * 64;    // 2 k-warps

    // ---- stage a_s / v_s (fp32, ones column) ----
    if (tid < T_) { a_s[tid * 50] = 1.f; v_s[tid * 50] = 1.f; }
    {
        const float* ab = audio + (size_t)b * T_ * A_;
        const float* vb = video + (size_t)b * T_ * V_;
        for (int idx = tid; idx < T_ * A_; idx += 256) {
            const int t = idx / A_;
            const int c = idx - t * A_;
            a_s[t * 50 + c + 1] = ab[idx];
            v_s[t * 50 + c + 1] = vb[idx];
        }
    }
    // ---- stage x1 bf16 hi/lo: [t][k], k==0 -> 1, k>=97 -> 0 ----
    {
        const float* xb = text + (size_t)b * T_ * X_;
#pragma unroll
        for (int i = 0; i < 32; i++) {
            const int idx = i * 256 + tid;
            const int t = idx >> 7;
            const int k = idx & 127;
            float xv = 0.f;
            if (k == 0)      xv = 1.f;
            else if (k < XK) xv = xb[t * X_ + k - 1];
            const __nv_bfloat16 h = __float2bfloat16(xv);
            const __nv_bfloat16 l =
                __float2bfloat16(xv - __bfloat162float(h));
            Bh[t * 136 + k] = h;
            Bl[t * 136 + k] = l;
        }
    }
    __syncthreads();

    // per-lane row identities: rows rA/rB per m-tile
    int ii[2][2], jj[2][2];
    float ok[2][2];
#pragma unroll
    for (int m = 0; m < 2; m++)
#pragma unroll
        for (int h = 0; h < 2; h++) {
            const int row = warp_ij + m * 16 + h * 8 + (lane >> 2);
            const int ij  = ijbase + row;
            const bool v  = (ij < IJ);
            ok[m][h] = v ? 1.f : 0.f;
            ii[m][h] = v ? (ij / VJ) : 0;
            jj[m][h] = v ? (ij - (ij / VJ) * VJ) : 0;
        }

    const uint32_t bHiB = smem_u32(Bh);
    const uint32_t bLoB = smem_u32(Bl);
    const int g  = lane >> 3;
    const int l8 = lane & 7;
    const int b_f  = (g & 1) * 8 + l8;
    const int b_po = (g >> 1) * 8;

    float acc[2][8][4];
#pragma unroll
    for (int m = 0; m < 2; m++)
#pragma unroll
        for (int n = 0; n < 8; n++)
#pragma unroll
            for (int j = 0; j < 4; j++) acc[m][n][j] = 0.f;

    const int tbase = 2 * (lane & 3);

#pragma unroll
    for (int ks = 0; ks < 4; ks++) {
        const int t0 = ks * 16 + tbase;
        // ---- A fragments in registers: av = a*v, split hi/lo ----
        uint32_t fah[2][4], fal[2][4];
#pragma unroll
        for (int m = 0; m < 2; m++) {
#pragma unroll
            for (int q = 0; q < 4; q++) {
                const int h  = q & 1;            // row half (+0 / +8)
                const int ko = (q >> 1) * 8;     // k offset (+0 / +8)
                const int t  = t0 + ko;
                const float f0 = ok[m][h] *
                    a_s[t * 50 + ii[m][h]] * v_s[t * 50 + jj[m][h]];
                const float f1 = ok[m][h] *
                    a_s[(t + 1) * 50 + ii[m][h]] * v_s[(t + 1) * 50 + jj[m][h]];
                split2(f0, f1, fah[m][q], fal[m][q]);
            }
        }
        // ---- B fragments via ldmatrix.x4.trans ----
        uint32_t fbh[8][2], fbl[8][2];
#pragma unroll
        for (int np = 0; np < 4; np++) {
            const uint32_t off =
                (uint32_t)((ks * 16 + b_f) * 272
                           + (warp_k + np * 16 + b_po) * 2);
            uint32_t r0, r1, r2, r3;
            ldsm_x4t(r0, r1, r2, r3, bHiB + off);
            fbh[np * 2][0] = r0; fbh[np * 2][1] = r1;
            fbh[np * 2 + 1][0] = r2; fbh[np * 2 + 1][1] = r3;
            ldsm_x4t(r0, r1, r2, r3, bLoB + off);
            fbl[np * 2][0] = r0; fbl[np * 2][1] = r1;
            fbl[np * 2 + 1][0] = r2; fbl[np * 2 + 1][1] = r3;
        }
        // ---- 3-pass MMAs ----
#pragma unroll
        for (int m = 0; m < 2; m++)
#pragma unroll
            for (int n = 0; n < 8; n++) {
                mma16816(acc[m][n], fah[m], fbh[n]);
                mma16816(acc[m][n], fah[m], fbl[n]);
                mma16816(acc[m][n], fal[m], fbh[n]);
            }
    }

    // ---- store (scalar STG: row stride 97 breaks float2 alignment) ----
#pragma unroll
    for (int m = 0; m < 2; m++)
#pragma unroll
        for (int h = 0; h < 2; h++) {
            const int row = warp_ij + m * 16 + h * 8 + (lane >> 2);
            const int ij  = ijbase + row;
            if (ij >= IJ) continue;
            float* dst = g_fusion + (size_t)b * FDP2 + (size_t)ij * XK;
#pragma unroll
            for (int n = 0; n < 8; n++) {
                const int col = warp_k + n * 8 + 2 * (lane & 3);
                if (col < XK)     dst[col]     = acc[m][n][h * 2];
                if (col + 1 < XK) dst[col + 1] = acc[m][n][h * 2 + 1];
            }
        }
}

// ---------------------------------------------------------------------------
// Stage 2: mma.sync split-K GEMM (unchanged R11 winner).
// ---------------------------------------------------------------------------
constexpr int APAD = 56;   // A row stride bf16 (112 B)
constexpr int BPAD = 72;   // B row stride bf16 (144 B)

__global__ void __launch_bounds__(256, 2)
gemm_mma(const float* __restrict__ W1)
{
    __shared__ __align__(16) __nv_bfloat16 Ahi[128][APAD];
    __shared__ __align__(16) __nv_bfloat16 Alo[128][APAD];
    __shared__ __align__(16) __nv_bfloat16 Bhi[KT][BPAD];
    __shared__ __align__(16) __nv_bfloat16 Blo[KT][BPAD];

    const int tid    = threadIdx.x;
    const int wid    = tid >> 5;
    const int lane   = tid & 31;
    const int kslice = blockIdx.x >> 1;
    const int phalf  = blockIdx.x & 1;
    const int warp_b = (wid >> 1) * 32;
    const int warp_p = (wid & 1) * 32;

    const uint32_t aHiB = smem_u32(&Ahi[0][0]);
    const uint32_t aLoB = smem_u32(&Alo[0][0]);
    const uint32_t bHiB = smem_u32(&Bhi[0][0]);
    const uint32_t bLoB = smem_u32(&Blo[0][0]);

    const int g   = lane >> 3;
    const int l8  = lane & 7;
    const int a_m  = (g & 1) * 8 + l8;
    const int a_ko = (g >> 1) * 8;
    const int b_f  = (g & 1) * 8 + l8;
    const int b_po = (g >> 1) * 8;

    float acc[2][4][4];
#pragma unroll
    for (int m = 0; m < 2; m++)
#pragma unroll
        for (int n = 0; n < 4; n++)
#pragma unroll
            for (int j = 0; j < 4; j++) acc[m][n][j] = 0.f;

    const int a_b  = tid >> 3;
    const int a_f4 = tid & 7;
    const int b_fr = tid >> 4;
    const int b_p4 = tid & 15;

    float4 pa[4], pb[2];
    int tile = kslice;
    {
        const int kb = tile * KT;
#pragma unroll
        for (int u = 0; u < 4; u++)
            pa[u] = *(const float4*)(g_fusion +
                     (size_t)(a_b + u * 32) * FDP2 + kb + a_f4 * 4);
#pragma unroll
        for (int u = 0; u < 2; u++) {
            const int f = kb + b_fr + u * 16;
            pb[u] = (f < FD)
                ? *(const float4*)(W1 + (size_t)f * PF + phalf * 64 + b_p4 * 4)
                : make_float4(0.f, 0.f, 0.f, 0.f);
        }
    }
#pragma unroll
    for (int u = 0; u < 4; u++) {
        uint2 hi, lo;
        split4(pa[u], hi, lo);
        *(uint2*)&Ahi[a_b + u * 32][a_f4 * 4] = hi;
        *(uint2*)&Alo[a_b + u * 32][a_f4 * 4] = lo;
    }
#pragma unroll
    for (int u = 0; u < 2; u++) {
        uint2 hi, lo;
        split4(pb[u], hi, lo);
        *(uint2*)&Bhi[b_fr + u * 16][b_p4 * 4] = hi;
        *(uint2*)&Blo[b_fr + u * 16][b_p4 * 4] = lo;
    }
    __syncthreads();

    while (true) {
        const int next = tile + NSPLIT;
        const bool has = (next < NT32);
        if (has) {
            const int kb = next * KT;
#pragma unroll
            for (int u = 0; u < 4; u++)
                pa[u] = *(const float4*)(g_fusion +
                         (size_t)(a_b + u * 32) * FDP2 + kb + a_f4 * 4);
#pragma unroll
            for (int u = 0; u < 2; u++) {
                const int f = kb + b_fr + u * 16;
                pb[u] = (f < FD)
                    ? *(const float4*)(W1 + (size_t)f * PF + phalf * 64 + b_p4 * 4)
                    : make_float4(0.f, 0.f, 0.f, 0.f);
            }
        }

#pragma unroll
        for (int ks = 0; ks < 2; ks++) {
            uint32_t fahi[2][4], falo[2][4];
#pragma unroll
            for (int m = 0; m < 2; m++) {
                const uint32_t off =
                    (uint32_t)((warp_b + m * 16 + a_m) * (APAD * 2)
                               + ks * 32 + a_ko * 2);
                ldsm_x4(fahi[m][0], fahi[m][1], fahi[m][2], fahi[m][3],
                        aHiB + off);
                ldsm_x4(falo[m][0], falo[m][1], falo[m][2], falo[m][3],
                        aLoB + off);
            }
            uint32_t fbhi[4][2], fblo[4][2];
#pragma unroll
            for (int np = 0; np < 2; np++) {
                const uint32_t off =
                    (uint32_t)((ks * 16 + b_f) * (BPAD * 2)
                               + (warp_p + np * 16 + b_po) * 2);
                uint32_t r0, r1, r2, r3;
                ldsm_x4t(r0, r1, r2, r3, bHiB + off);
                fbhi[np * 2][0] = r0; fbhi[np * 2][1] = r1;
                fbhi[np * 2 + 1][0] = r2; fbhi[np * 2 + 1][1] = r3;
                ldsm_x4t(r0, r1, r2, r3, bLoB + off);
                fblo[np * 2][0] = r0; fblo[np * 2][1] = r1;
                fblo[np * 2 + 1][0] = r2; fblo[np * 2 + 1][1] = r3;
            }
#pragma unroll
            for (int m = 0; m < 2; m++)
#pragma unroll
                for (int n = 0; n < 4; n++) {
                    mma16816(acc[m][n], fahi[m], fbhi[n]);
                    mma16816(acc[m][n], fahi[m], fblo[n]);
                    mma16816(acc[m][n], falo[m], fbhi[n]);
                }
        }

        if (!has) break;
        __syncthreads();
#pragma unroll
        for (int u = 0; u < 4; u++) {
            uint2 hi, lo;
            split4(pa[u], hi, lo);
            *(uint2*)&Ahi[a_b + u * 32][a_f4 * 4] = hi;
            *(uint2*)&Alo[a_b + u * 32][a_f4 * 4] = lo;
        }
#pragma unroll
        for (int u = 0; u < 2; u++) {
            uint2 hi, lo;
            split4(pb[u], hi, lo);
            *(uint2*)&Bhi[b_fr + u * 16][b_p4 * 4] = hi;
            *(uint2*)&Blo[b_fr + u * 16][b_p4 * 4] = lo;
        }
        __syncthreads();
        tile = next;
    }

    float* base = g_part + (size_t)kslice * (B_ * PF) + phalf * 64;
#pragma unroll
    for (int m = 0; m < 2; m++) {
        const int b0 = warp_b + m * 16 + (lane >> 2);
#pragma unroll
        for (int n = 0; n < 4; n++) {
            const int p = warp_p + n * 8 + 2 * (lane & 3);
            *(float2*)(base + (size_t)b0 * PF + p) =
                make_float2(acc[m][n][0], acc[m][n][1]);
            *(float2*)(base + (size_t)(b0 + 8) * PF + p) =
                make_float2(acc[m][n][2], acc[m][n][3]);
        }
    }
}

// ---------------------------------------------------------------------------
// Stage 3: reduce partials -> h1 (relu) -> h2 (relu) -> sigmoid*6-3.
// ---------------------------------------------------------------------------
__global__ void __launch_bounds__(128)
mlp_kernel(const float* __restrict__ b1,
           const float* __restrict__ W2,
           const float* __restrict__ b2,
           const float* __restrict__ W3,
           const float* __restrict__ b3,
           float* __restrict__ out)
{
    __shared__ float h1[128];
    __shared__ float red[128];
    const int b = blockIdx.x;
    const int p = threadIdx.x;

    float s = b1[p];
    const float* pp = g_part + (size_t)b * PF + p;
#pragma unroll 8
    for (int c = 0; c < NSPLIT; c++) s += pp[(size_t)c * B_ * PF];
    h1[p] = fmaxf(s, 0.f);
    __syncthreads();

    float s2 = b2[p];
#pragma unroll 8
    for (int q = 0; q < PF; q++) s2 = fmaf(h1[q], W2[q * PF + p], s2);
    const float h2 = fmaxf(s2, 0.f);

    red[p] = h2 * W3[p];
    __syncthreads();
    for (int st = 64; st > 0; st >>= 1) {
        if (p < st) red[p] += red[p + st];
        __syncthreads();
    }
    if (p == 0) {
        const float z = red[0] + b3[0];
        out[b] = 6.f / (1.f + expf(-z)) - 3.f;
    }
}

// ---------------------------------------------------------------------------
extern "C" void kernel_launch(void* const* d_in, const int* in_sizes, int n_in,
                              void* d_out, int out_size)
{
    const float* audio = (const float*)d_in[0];
    const float* video = (const float*)d_in[1];
    const float* text  = (const float*)d_in[2];
    const float* W1    = (const float*)d_in[3];
    const float* b1    = (const float*)d_in[4];
    const float* W2    = (const float*)d_in[5];
    const float* b2    = (const float*)d_in[6];
    const float* W3    = (const float*)d_in[7];
    const float* b3    = (const float*)d_in[8];

    cudaFuncSetAttribute(fusion_mma,
                         cudaFuncAttributeMaxDynamicSharedMemorySize, FS_TOTAL);

    fusion_mma<<<dim3(19, B_), 256, FS_TOTAL>>>(audio, video, text);
    gemm_mma<<<2 * NSPLIT, 256>>>(W1);
    mlp_kernel<<<B_, 128>>>(b1, W2, b2, W3, b3, (float*)d_out);
}

// round 15
// speedup vs baseline: 1.1584x; 1.1584x over previous
#include <cuda_runtime.h>
#include <cuda_bf16.h>
#include <cstdint>

// ---------------------------------------------------------------------------
// T2FN: fusion = sum_t (a1 ⊗ v1 ⊗ x1)  [B, 49*49*97], then 3-layer MLP.
// Stage 1 (fusion_mma v2): per-b GEMM av[2401x64] @ x1[64x97] on mma.sync,
//   bf16 3-pass hi/lo split, fp32 acc. av staged in smem bf16 hi/lo per 16-t
//   chunk (shared by all k-warps, ldmatrix-fed); 512 thr, 16 warps (4ij x 4k),
//   warp tile 32x32 -> ~110 regs, 16 warps/SM.
// Stage 2 (gemm_mma): split-K GEMM fusion[128,FD] @ W1[FD,128], mma.sync,
//   3-pass bf16 split (unchanged R11 winner).
// Stage 3 (mlp): reduce partials + bias/relu chain + sigmoid*6-3.
// NOTE: tcgen05 unavailable (harness targets compute_103, not 103a).
// ---------------------------------------------------------------------------

typedef unsigned long long u64;

constexpr int B_  = 128;
constexpr int T_  = 64;
constexpr int A_  = 48;
constexpr int V_  = 48;
constexpr int X_  = 96;
constexpr int AI  = A_ + 1;      // 49
constexpr int VJ  = V_ + 1;      // 49
constexpr int XK  = X_ + 1;      // 97
constexpr int IJ  = AI * VJ;     // 2401
constexpr int FD  = IJ * XK;     // 232897
constexpr int FDP2 = 232960;     // FD padded to multiple of 64
constexpr int PF  = 128;
constexpr int NSPLIT = 296;      // K-slices
constexpr int KT  = 32;          // GEMM K-tile
constexpr int NT32 = FDP2 / KT;  // 7280

__device__ float g_fusion[(size_t)B_ * FDP2];        // ~119 MB (pad stays 0)
__device__ float g_part[(size_t)NSPLIT * B_ * PF];   // ~19.4 MB

// ---------------------------------------------------------------------------
// common mma helpers
// ---------------------------------------------------------------------------
__device__ __forceinline__ uint32_t smem_u32(const void* p) {
    uint32_t a;
    asm("{ .reg .u64 t; cvta.to.shared.u64 t, %1; cvt.u32.u64 %0, t; }"
        : "=r"(a) : "l"(p));
    return a;
}
__device__ __forceinline__ void ldsm_x4(uint32_t& r0, uint32_t& r1,
                                        uint32_t& r2, uint32_t& r3,
                                        uint32_t addr) {
    asm volatile("ldmatrix.sync.aligned.m8n8.x4.shared.b16 {%0,%1,%2,%3}, [%4];"
                 : "=r"(r0), "=r"(r1), "=r"(r2), "=r"(r3) : "r"(addr));
}
__device__ __forceinline__ void ldsm_x4t(uint32_t& r0, uint32_t& r1,
                                         uint32_t& r2, uint32_t& r3,
                                         uint32_t addr) {
    asm volatile("ldmatrix.sync.aligned.m8n8.x4.trans.shared.b16 {%0,%1,%2,%3}, [%4];"
                 : "=r"(r0), "=r"(r1), "=r"(r2), "=r"(r3) : "r"(addr));
}
__device__ __forceinline__ void mma16816(float* c, const uint32_t* a,
                                         const uint32_t* b) {
    asm volatile(
        "mma.sync.aligned.m16n8k16.row.col.f32.bf16.bf16.f32 "
        "{%0,%1,%2,%3}, {%4,%5,%6,%7}, {%8,%9}, {%0,%1,%2,%3};"
        : "+f"(c[0]), "+f"(c[1]), "+f"(c[2]), "+f"(c[3])
        : "r"(a[0]), "r"(a[1]), "r"(a[2]), "r"(a[3]), "r"(b[0]), "r"(b[1]));
}
__device__ __forceinline__ void split4(float4 v, uint2& hi, uint2& lo) {
    __nv_bfloat162 h01 = __float22bfloat162_rn(make_float2(v.x, v.y));
    __nv_bfloat162 h23 = __float22bfloat162_rn(make_float2(v.z, v.w));
    __nv_bfloat162 l01 = __float22bfloat162_rn(make_float2(
        v.x - __bfloat162float(h01.x), v.y - __bfloat162float(h01.y)));
    __nv_bfloat162 l23 = __float22bfloat162_rn(make_float2(
        v.z - __bfloat162float(h23.x), v.w - __bfloat162float(h23.y)));
    hi = make_uint2(*(uint32_t*)&h01, *(uint32_t*)&h23);
    lo = make_uint2(*(uint32_t*)&l01, *(uint32_t*)&l23);
}
__device__ __forceinline__ void split2(float f0, float f1,
                                       uint32_t& h, uint32_t& l) {
    __nv_bfloat162 hh = __float22bfloat162_rn(make_float2(f0, f1));
    __nv_bfloat162 ll = __float22bfloat162_rn(make_float2(
        f0 - __bfloat162float(hh.x), f1 - __bfloat162float(hh.y)));
    h = *(uint32_t*)&hh;
    l = *(uint32_t*)&ll;
}

// ---------------------------------------------------------------------------
// Stage 1: fusion via mma.sync, smem-staged av.
// grid = (19 ij-tiles, 128 b), 512 threads, 16 warps = 4 ij x 4 k.
// CTA tile 128 ij x 128 k (valid k < 97); K loop = 4 chunks of 16 t.
// ---------------------------------------------------------------------------
constexpr int AVP = 24;                    // av row stride bf16 (48 B: 3 mod 8)
constexpr int FS_AS = 0;                   // [64][50] fp32  (12800 B)
constexpr int FS_VS = 12800;               // [64][50] fp32  (12800 B)
constexpr int FS_BH = 25600;               // [64][136] bf16 (17408 B)
constexpr int FS_BL = 43008;               // [64][136] bf16 (17408 B)
constexpr int FS_AH = 60416;               // [128][24] bf16 (6144 B)
constexpr int FS_AL = 66560;               // [128][24] bf16 (6144 B)
constexpr int FS_TOTAL = 72704;

__global__ void __launch_bounds__(512, 1)
fusion_mma(const float* __restrict__ audio,
           const float* __restrict__ video,
           const float* __restrict__ text)
{
    extern __shared__ __align__(16) char sm[];
    float* a_s = (float*)(sm + FS_AS);
    float* v_s = (float*)(sm + FS_VS);
    __nv_bfloat16* Bh = (__nv_bfloat16*)(sm + FS_BH);
    __nv_bfloat16* Bl = (__nv_bfloat16*)(sm + FS_BL);

    const int b      = blockIdx.y;
    const int ijbase = blockIdx.x * 128;
    const int tid    = threadIdx.x;
    const int wid    = tid >> 5;
    const int lane   = tid & 31;
    const int warp_ij = (wid >> 2) * 32;   // 4 ij-warps
    const int warp_k  = (wid & 3) * 32;    // 4 k-warps

    // ---- stage a_s / v_s (fp32, ones column) ----
    if (tid < T_) { a_s[tid * 50] = 1.f; v_s[tid * 50] = 1.f; }
    {
        const float* ab = audio + (size_t)b * T_ * A_;
        const float* vb = video + (size_t)b * T_ * V_;
        for (int idx = tid; idx < T_ * A_; idx += 512) {
            const int t = idx / A_;
            const int c = idx - t * A_;
            a_s[t * 50 + c + 1] = ab[idx];
            v_s[t * 50 + c + 1] = vb[idx];
        }
    }
    // ---- stage x1 bf16 hi/lo: [t][k], k==0 -> 1, k>=97 -> 0 ----
    {
        const float* xb = text + (size_t)b * T_ * X_;
#pragma unroll
        for (int i = 0; i < 16; i++) {
            const int idx = i * 512 + tid;
            const int t = idx >> 7;
            const int k = idx & 127;
            float xv = 0.f;
            if (k == 0)      xv = 1.f;
            else if (k < XK) xv = xb[t * X_ + k - 1];
            const __nv_bfloat16 h = __float2bfloat16(xv);
            const __nv_bfloat16 l =
                __float2bfloat16(xv - __bfloat162float(h));
            Bh[t * 136 + k] = h;
            Bl[t * 136 + k] = l;
        }
    }

    // av-build identity: this thread computes row my_ij, t-slots my_th*4..+3
    const int  my_ij = tid & 127;
    const int  my_th = tid >> 7;           // 0..3
    const int  gij   = ijbase + my_ij;
    const bool vok   = (gij < IJ);
    const int  mii   = vok ? (gij / VJ) : 0;
    const int  mjj   = vok ? (gij - mii * VJ) : 0;

    const uint32_t bHiB = smem_u32(Bh);
    const uint32_t bLoB = smem_u32(Bl);
    const uint32_t aHiB = smem_u32(sm + FS_AH);
    const uint32_t aLoB = smem_u32(sm + FS_AL);
    __nv_bfloat16* Ah = (__nv_bfloat16*)(sm + FS_AH);
    __nv_bfloat16* Al = (__nv_bfloat16*)(sm + FS_AL);

    const int g  = lane >> 3;
    const int l8 = lane & 7;
    const int a_m  = (g & 1) * 8 + l8;     // A ldmatrix row-in-tile
    const int a_ko = (g >> 1) * 8;         // A ldmatrix t-half
    const int b_f  = (g & 1) * 8 + l8;     // B ldmatrix t row
    const int b_po = (g >> 1) * 8;         // B ldmatrix k offset

    float acc[2][4][4];
#pragma unroll
    for (int m = 0; m < 2; m++)
#pragma unroll
        for (int n = 0; n < 4; n++)
#pragma unroll
            for (int j = 0; j < 4; j++) acc[m][n][j] = 0.f;

    __syncthreads();

#pragma unroll
    for (int ks = 0; ks < 4; ks++) {
        // ---- build av chunk [128 ij][16 t] bf16 hi/lo ----
#pragma unroll
        for (int q = 0; q < 2; q++) {
            const int tc = my_th * 4 + q * 2;       // t within chunk
            const int t  = ks * 16 + tc;
            float f0 = 0.f, f1 = 0.f;
            if (vok) {
                f0 = a_s[t * 50 + mii] * v_s[t * 50 + mjj];
                f1 = a_s[(t + 1) * 50 + mii] * v_s[(t + 1) * 50 + mjj];
            }
            uint32_t h, l;
            split2(f0, f1, h, l);
            *(uint32_t*)&Ah[my_ij * AVP + tc] = h;
            *(uint32_t*)&Al[my_ij * AVP + tc] = l;
        }
        __syncthreads();

        // ---- A fragments via ldmatrix ----
        uint32_t fah[2][4], fal[2][4];
#pragma unroll
        for (int m = 0; m < 2; m++) {
            const uint32_t off =
                (uint32_t)((warp_ij + m * 16 + a_m) * (AVP * 2) + a_ko * 2);
            ldsm_x4(fah[m][0], fah[m][1], fah[m][2], fah[m][3], aHiB + off);
            ldsm_x4(fal[m][0], fal[m][1], fal[m][2], fal[m][3], aLoB + off);
        }
        // ---- B fragments via ldmatrix.x4.trans ----
        uint32_t fbh[4][2], fbl[4][2];
#pragma unroll
        for (int np = 0; np < 2; np++) {
            const uint32_t off =
                (uint32_t)((ks * 16 + b_f) * 272
                           + (warp_k + np * 16 + b_po) * 2);
            uint32_t r0, r1, r2, r3;
            ldsm_x4t(r0, r1, r2, r3, bHiB + off);
            fbh[np * 2][0] = r0; fbh[np * 2][1] = r1;
            fbh[np * 2 + 1][0] = r2; fbh[np * 2 + 1][1] = r3;
            ldsm_x4t(r0, r1, r2, r3, bLoB + off);
            fbl[np * 2][0] = r0; fbl[np * 2][1] = r1;
            fbl[np * 2 + 1][0] = r2; fbl[np * 2 + 1][1] = r3;
        }
        // ---- 3-pass MMAs ----
#pragma unroll
        for (int m = 0; m < 2; m++)
#pragma unroll
            for (int n = 0; n < 4; n++) {
                mma16816(acc[m][n], fah[m], fbh[n]);
                mma16816(acc[m][n], fah[m], fbl[n]);
                mma16816(acc[m][n], fal[m], fbh[n]);
            }
        __syncthreads();
    }

    // ---- store (scalar STG: row stride 97 breaks float2 alignment) ----
#pragma unroll
    for (int m = 0; m < 2; m++)
#pragma unroll
        for (int h = 0; h < 2; h++) {
            const int row = warp_ij + m * 16 + h * 8 + (lane >> 2);
            const int ij  = ijbase + row;
            if (ij >= IJ) continue;
            float* dst = g_fusion + (size_t)b * FDP2 + (size_t)ij * XK;
#pragma unroll
            for (int n = 0; n < 4; n++) {
                const int col = warp_k + n * 8 + 2 * (lane & 3);
                if (col < XK)     dst[col]     = acc[m][n][h * 2];
                if (col + 1 < XK) dst[col + 1] = acc[m][n][h * 2 + 1];
            }
        }
}

// ---------------------------------------------------------------------------
// Stage 2: mma.sync split-K GEMM (unchanged R11 winner).
// ---------------------------------------------------------------------------
constexpr int APAD = 56;   // A row stride bf16 (112 B)
constexpr int BPAD = 72;   // B row stride bf16 (144 B)

__global__ void __launch_bounds__(256, 2)
gemm_mma(const float* __restrict__ W1)
{
    __shared__ __align__(16) __nv_bfloat16 Ahi[128][APAD];
    __shared__ __align__(16) __nv_bfloat16 Alo[128][APAD];
    __shared__ __align__(16) __nv_bfloat16 Bhi[KT][BPAD];
    __shared__ __align__(16) __nv_bfloat16 Blo[KT][BPAD];

    const int tid    = threadIdx.x;
    const int wid    = tid >> 5;
    const int lane   = tid & 31;
    const int kslice = blockIdx.x >> 1;
    const int phalf  = blockIdx.x & 1;
    const int warp_b = (wid >> 1) * 32;
    const int warp_p = (wid & 1) * 32;

    const uint32_t aHiB = smem_u32(&Ahi[0][0]);
    const uint32_t aLoB = smem_u32(&Alo[0][0]);
    const uint32_t bHiB = smem_u32(&Bhi[0][0]);
    const uint32_t bLoB = smem_u32(&Blo[0][0]);

    const int g   = lane >> 3;
    const int l8  = lane & 7;
    const int a_m  = (g & 1) * 8 + l8;
    const int a_ko = (g >> 1) * 8;
    const int b_f  = (g & 1) * 8 + l8;
    const int b_po = (g >> 1) * 8;

    float acc[2][4][4];
#pragma unroll
    for (int m = 0; m < 2; m++)
#pragma unroll
        for (int n = 0; n < 4; n++)
#pragma unroll
            for (int j = 0; j < 4; j++) acc[m][n][j] = 0.f;

    const int a_b  = tid >> 3;
    const int a_f4 = tid & 7;
    const int b_fr = tid >> 4;
    const int b_p4 = tid & 15;

    float4 pa[4], pb[2];
    int tile = kslice;
    {
        const int kb = tile * KT;
#pragma unroll
        for (int u = 0; u < 4; u++)
            pa[u] = *(const float4*)(g_fusion +
                     (size_t)(a_b + u * 32) * FDP2 + kb + a_f4 * 4);
#pragma unroll
        for (int u = 0; u < 2; u++) {
            const int f = kb + b_fr + u * 16;
            pb[u] = (f < FD)
                ? *(const float4*)(W1 + (size_t)f * PF + phalf * 64 + b_p4 * 4)
                : make_float4(0.f, 0.f, 0.f, 0.f);
        }
    }
#pragma unroll
    for (int u = 0; u < 4; u++) {
        uint2 hi, lo;
        split4(pa[u], hi, lo);
        *(uint2*)&Ahi[a_b + u * 32][a_f4 * 4] = hi;
        *(uint2*)&Alo[a_b + u * 32][a_f4 * 4] = lo;
    }
#pragma unroll
    for (int u = 0; u < 2; u++) {
        uint2 hi, lo;
        split4(pb[u], hi, lo);
        *(uint2*)&Bhi[b_fr + u * 16][b_p4 * 4] = hi;
        *(uint2*)&Blo[b_fr + u * 16][b_p4 * 4] = lo;
    }
    __syncthreads();

    while (true) {
        const int next = tile + NSPLIT;
        const bool has = (next < NT32);
        if (has) {
            const int kb = next * KT;
#pragma unroll
            for (int u = 0; u < 4; u++)
                pa[u] = *(const float4*)(g_fusion +
                         (size_t)(a_b + u * 32) * FDP2 + kb + a_f4 * 4);
#pragma unroll
            for (int u = 0; u < 2; u++) {
                const int f = kb + b_fr + u * 16;
                pb[u] = (f < FD)
                    ? *(const float4*)(W1 + (size_t)f * PF + phalf * 64 + b_p4 * 4)
                    : make_float4(0.f, 0.f, 0.f, 0.f);
            }
        }

#pragma unroll
        for (int ks = 0; ks < 2; ks++) {
            uint32_t fahi[2][4], falo[2][4];
#pragma unroll
            for (int m = 0; m < 2; m++) {
                const uint32_t off =
                    (uint32_t)((warp_b + m * 16 + a_m) * (APAD * 2)
                               + ks * 32 + a_ko * 2);
                ldsm_x4(fahi[m][0], fahi[m][1], fahi[m][2], fahi[m][3],
                        aHiB + off);
                ldsm_x4(falo[m][0], falo[m][1], falo[m][2], falo[m][3],
                        aLoB + off);
            }
            uint32_t fbhi[4][2], fblo[4][2];
#pragma unroll
            for (int np = 0; np < 2; np++) {
                const uint32_t off =
                    (uint32_t)((ks * 16 + b_f) * (BPAD * 2)
                               + (warp_p + np * 16 + b_po) * 2);
                uint32_t r0, r1, r2, r3;
                ldsm_x4t(r0, r1, r2, r3, bHiB + off);
                fbhi[np * 2][0] = r0; fbhi[np * 2][1] = r1;
                fbhi[np * 2 + 1][0] = r2; fbhi[np * 2 + 1][1] = r3;
                ldsm_x4t(r0, r1, r2, r3, bLoB + off);
                fblo[np * 2][0] = r0; fblo[np * 2][1] = r1;
                fblo[np * 2 + 1][0] = r2; fblo[np * 2 + 1][1] = r3;
            }
#pragma unroll
            for (int m = 0; m < 2; m++)
#pragma unroll
                for (int n = 0; n < 4; n++) {
                    mma16816(acc[m][n], fahi[m], fbhi[n]);
                    mma16816(acc[m][n], fahi[m], fblo[n]);
                    mma16816(acc[m][n], falo[m], fbhi[n]);
                }
        }

        if (!has) break;
        __syncthreads();
#pragma unroll
        for (int u = 0; u < 4; u++) {
            uint2 hi, lo;
            split4(pa[u], hi, lo);
            *(uint2*)&Ahi[a_b + u * 32][a_f4 * 4] = hi;
            *(uint2*)&Alo[a_b + u * 32][a_f4 * 4] = lo;
        }
#pragma unroll
        for (int u = 0; u < 2; u++) {
            uint2 hi, lo;
            split4(pb[u], hi, lo);
            *(uint2*)&Bhi[b_fr + u * 16][b_p4 * 4] = hi;
            *(uint2*)&Blo[b_fr + u * 16][b_p4 * 4] = lo;
        }
        __syncthreads();
        tile = next;
    }

    float* base = g_part + (size_t)kslice * (B_ * PF) + phalf * 64;
#pragma unroll
    for (int m = 0; m < 2; m++) {
        const int b0 = warp_b + m * 16 + (lane >> 2);
#pragma unroll
        for (int n = 0; n < 4; n++) {
            const int p = warp_p + n * 8 + 2 * (lane & 3);
            *(float2*)(base + (size_t)b0 * PF + p) =
                make_float2(acc[m][n][0], acc[m][n][1]);
            *(float2*)(base + (size_t)(b0 + 8) * PF + p) =
                make_float2(acc[m][n][2], acc[m][n][3]);
        }
    }
}

// ---------------------------------------------------------------------------
// Stage 3: reduce partials -> h1 (relu) -> h2 (relu) -> sigmoid*6-3.
// ---------------------------------------------------------------------------
__global__ void __launch_bounds__(128)
mlp_kernel(const float* __restrict__ b1,
           const float* __restrict__ W2,
           const float* __restrict__ b2,
           const float* __restrict__ W3,
           const float* __restrict__ b3,
           float* __restrict__ out)
{
    __shared__ float h1[128];
    __shared__ float red[128];
    const int b = blockIdx.x;
    const int p = threadIdx.x;

    float s = b1[p];
    const float* pp = g_part + (size_t)b * PF + p;
#pragma unroll 8
    for (int c = 0; c < NSPLIT; c++) s += pp[(size_t)c * B_ * PF];
    h1[p] = fmaxf(s, 0.f);
    __syncthreads();

    float s2 = b2[p];
#pragma unroll 8
    for (int q = 0; q < PF; q++) s2 = fmaf(h1[q], W2[q * PF + p], s2);
    const float h2 = fmaxf(s2, 0.f);

    red[p] = h2 * W3[p];
    __syncthreads();
    for (int st = 64; st > 0; st >>= 1) {
        if (p < st) red[p] += red[p + st];
        __syncthreads();
    }
    if (p == 0) {
        const float z = red[0] + b3[0];
        out[b] = 6.f / (1.f + expf(-z)) - 3.f;
    }
}

// ---------------------------------------------------------------------------
extern "C" void kernel_launch(void* const* d_in, const int* in_sizes, int n_in,
                              void* d_out, int out_size)
{
    const float* audio = (const float*)d_in[0];
    const float* video = (const float*)d_in[1];
    const float* text  = (const float*)d_in[2];
    const float* W1    = (const float*)d_in[3];
    const float* b1    = (const float*)d_in[4];
    const float* W2    = (const float*)d_in[5];
    const float* b2    = (const float*)d_in[6];
    const float* W3    = (const float*)d_in[7];
    const float* b3    = (const float*)d_in[8];

    cudaFuncSetAttribute(fusion_mma,
                         cudaFuncAttributeMaxDynamicSharedMemorySize, FS_TOTAL);

    fusion_mma<<<dim3(19, B_), 512, FS_TOTAL>>>(audio, video, text);
    gemm_mma<<<2 * NSPLIT, 256>>>(W1);
    mlp_kernel<<<B_, 128>>>(b1, W2, b2, W3, b3, (float*)d_out);
}